// round 10
// baseline (speedup 1.0000x reference)
#include <cuda_runtime.h>
#include <cstdint>

#define N_ENTITIES 100000
#define N_USERS    50000
#define N_FACTORS  4
#define N_RELATIONS 32
#define N_REL_USED 31
#define N_META     8
#define CHANNEL    64
#define N_EDGES    1600000
#define NNZ_CNT    1000000

// edge scatter (solo kernel)
#define EDGE_BLOCKS 888
#define HW_PER_BLOCK 16                     // 256 threads / 16 lanes

// spmm scatter (solo kernel, side stream)
#define SPMM_BLOCKS 444

// prep kernel split
#define ZERO_BLOCKS 296                     // zero entity rows + g_cnt
#define ATT_BLOCKS  888
#define PREP_BLOCKS (ZERO_BLOCKS + ATT_BLOCKS + 1)   // +1 block for disen

#define TILE_E 64                            // entities staged per block tile
#define ATT_TILES ((N_ENTITIES + TILE_E - 1) / TILE_E)

// final kernel split
#define ENTF_BLOCKS 6250     // entity mean: 1.6M float4 / 256
#define USERF_BLOCKS 6250    // users: 50000 / 8 warps
#define FINAL_BLOCKS (ENTF_BLOCKS + USERF_BLOCKS)

// ------------------------- device-global scratch ---------------------------
__device__ float g_cnt[N_ENTITIES];
__device__ float g_disen[N_FACTORS * CHANNEL];
__device__ float g_att[N_ENTITIES * N_REL_USED];   // sigmoid(ent[h] . rel[r])

__device__ __forceinline__ void red_add_v4(float* p, float x, float y, float z, float w) {
    asm volatile("red.global.add.v4.f32 [%0], {%1,%2,%3,%4};"
                 :: "l"(p), "f"(x), "f"(y), "f"(z), "f"(w) : "memory");
}

// ---------------------------------------------------------------------------
// 1) PREP (stream 0): zero entity accumulators | att table | disen
// ---------------------------------------------------------------------------
__global__ void __launch_bounds__(256)
prep_kernel(const float* __restrict__ ent,
            const float* __restrict__ relw,
            const float* __restrict__ datt,
            const float* __restrict__ weight,
            float4* __restrict__ out_ent4) {
    int b = blockIdx.x;

    if (b < ZERO_BLOCKS) {
        // ---- zero entity output + counts ----
        const int total4 = N_ENTITIES * CHANNEL / 4;
        int i0     = b * 256 + threadIdx.x;
        int stride = ZERO_BLOCKS * 256;
        for (int i = i0; i < total4; i += stride)
            out_ent4[i] = make_float4(0.f, 0.f, 0.f, 0.f);
        for (int i = i0; i < N_ENTITIES; i += stride)
            g_cnt[i] = 0.0f;

    } else if (b < ZERO_BLOCKS + ATT_BLOCKS) {
        // ---- attention table: tile staging + register-resident rel ----
        __shared__ float s_ent[TILE_E * CHANNEL];     // 16 KB tile
        int lane = threadIdx.x & 31;
        int wid  = threadIdx.x >> 5;

        float4 rrel[16];
        if (lane < N_REL_USED) {
            const float4* rw = (const float4*)&relw[lane * CHANNEL];
            #pragma unroll
            for (int i = 0; i < 16; i++) rrel[i] = __ldg(&rw[i]);
        } else {
            #pragma unroll
            for (int i = 0; i < 16; i++) rrel[i] = make_float4(0.f, 0.f, 0.f, 0.f);
        }

        int tile0 = b - ZERO_BLOCKS;
        for (int tile = tile0; tile < ATT_TILES; tile += ATT_BLOCKS) {
            int base = tile * TILE_E;
            int cnt  = min(TILE_E, N_ENTITIES - base);

            __syncthreads();                          // protect prior tile reads
            const float4* src = (const float4*)&ent[(size_t)base * CHANNEL];
            for (int i = threadIdx.x; i < cnt * (CHANNEL / 4); i += 256)
                ((float4*)s_ent)[i] = __ldg(&src[i]); // coalesced stream
            __syncthreads();

            for (int k = wid; k < cnt; k += 8) {
                const float4* row = (const float4*)&s_ent[k * CHANNEL];
                float d0 = 0.f, d1 = 0.f, d2 = 0.f, d3 = 0.f;
                #pragma unroll
                for (int i = 0; i < 16; i++) {
                    float4 a = row[i];                // broadcast LDS.128 (N=1)
                    d0 += a.x * rrel[i].x;
                    d1 += a.y * rrel[i].y;
                    d2 += a.z * rrel[i].z;
                    d3 += a.w * rrel[i].w;
                }
                float d = (d0 + d1) + (d2 + d3);
                if (lane < N_REL_USED)
                    g_att[(size_t)(base + k) * N_REL_USED + lane] =
                        1.0f / (1.0f + __expf(-d));
            }
        }

    } else {
        // ---- disen_weight = softmax(disen_weight_att, -1) @ weight ----
        int c = threadIdx.x;
        if (c >= CHANNEL) return;
        #pragma unroll
        for (int f = 0; f < N_FACTORS; f++) {
            float a[N_META];
            float m = -1e30f;
            #pragma unroll
            for (int j = 0; j < N_META; j++) { a[j] = datt[f * N_META + j]; m = fmaxf(m, a[j]); }
            float s = 0.0f;
            #pragma unroll
            for (int j = 0; j < N_META; j++) { a[j] = __expf(a[j] - m); s += a[j]; }
            float inv = 1.0f / s;
            float acc = 0.0f;
            #pragma unroll
            for (int j = 0; j < N_META; j++) acc += a[j] * inv * weight[j * CHANNEL + c];
            g_disen[f * CHANNEL + c] = acc;
        }
    }
}

// ---------------------------------------------------------------------------
// 2a) zero user accumulator (side stream, before spmm)
// ---------------------------------------------------------------------------
__global__ void zero_user_kernel(float4* __restrict__ out_user4) {
    int i = blockIdx.x * blockDim.x + threadIdx.x;
    if (i < N_USERS * CHANNEL / 4)
        out_user4[i] = make_float4(0.f, 0.f, 0.f, 0.f);
}

// ---------------------------------------------------------------------------
// 2b) spmm scatter (side stream): overlaps with prep on stream 0
// ---------------------------------------------------------------------------
__global__ void __launch_bounds__(256)
spmm_kernel(const float* __restrict__ ent,
            const int*   __restrict__ mrow,
            const int*   __restrict__ mcol,
            const float* __restrict__ mval,
            float* __restrict__ out_user) {
    int li     = threadIdx.x & 15;
    int hw     = blockIdx.x * HW_PER_BLOCK + (threadIdx.x >> 4);
    int stride = SPMM_BLOCKS * HW_PER_BLOCK;

    for (int i = hw; i < NNZ_CNT; i += stride) {
        int   r = __ldg(&mrow[i]);
        int   c = __ldg(&mcol[i]);
        float v = __ldg(&mval[i]);
        float4 e4 = __ldg((const float4*)&ent[(size_t)c * CHANNEL + li * 4]);
        red_add_v4(&out_user[(size_t)r * CHANNEL + li * 4],
                   v * e4.x, v * e4.y, v * e4.z, v * e4.w);
    }
}

// ---------------------------------------------------------------------------
// 3) edge scatter (stream 0, after prep): at the LTS atomic roofline
// ---------------------------------------------------------------------------
__global__ void __launch_bounds__(256)
edge_kernel(const float* __restrict__ ent,
            const int*   __restrict__ head,
            const int*   __restrict__ tail,
            const int*   __restrict__ etype,
            const float* __restrict__ relw,
            float* __restrict__ out_ent) {
    __shared__ float s_rel[N_REL_USED * CHANNEL];
    for (int i = threadIdx.x; i < N_REL_USED * CHANNEL; i += blockDim.x)
        s_rel[i] = relw[i];
    __syncthreads();

    int li     = threadIdx.x & 15;
    int hw     = blockIdx.x * HW_PER_BLOCK + (threadIdx.x >> 4);
    int stride = EDGE_BLOCKS * HW_PER_BLOCK;

    for (int e = hw; e < N_EDGES; e += stride) {
        int h  = __ldg(&head[e]);
        int t  = __ldg(&tail[e]);
        int ri = __ldg(&etype[e]) - 1;

        float  att = __ldg(&g_att[h * N_REL_USED + ri]);
        float4 rel = *(const float4*)&s_rel[ri * CHANNEL + li * 4];
        float4 et  = __ldg((const float4*)&ent[(size_t)t * CHANNEL + li * 4]);

        red_add_v4(&out_ent[(size_t)h * CHANNEL + li * 4],
                   att * et.x * rel.x, att * et.y * rel.y,
                   att * et.z * rel.z, att * et.w * rel.w);
        if (li == 0)
            asm volatile("red.global.add.f32 [%0], %1;"
                         :: "l"(&g_cnt[h]), "f"(1.0f) : "memory");
    }
}

// ---------------------------------------------------------------------------
// 4) FINAL: entity mean-divide | user softmax-blend  (block-split)
// ---------------------------------------------------------------------------
__global__ void __launch_bounds__(256)
final_kernel(const float* __restrict__ user_emb,
             const float* __restrict__ latent,
             float4* __restrict__ out_ent4,
             float* __restrict__ out_user) {
    int b = blockIdx.x;

    if (b < ENTF_BLOCKS) {
        int i = b * 256 + threadIdx.x;
        if (i >= N_ENTITIES * (CHANNEL / 4)) return;
        float inv = 1.0f / fmaxf(g_cnt[i >> 4], 1.0f);
        float4 v = out_ent4[i];
        v.x *= inv; v.y *= inv; v.z *= inv; v.w *= inv;
        out_ent4[i] = v;

    } else {
        __shared__ float s_lat[N_FACTORS * CHANNEL];
        __shared__ float s_dis[N_FACTORS * CHANNEL];
        for (int i = threadIdx.x; i < N_FACTORS * CHANNEL; i += blockDim.x) {
            s_lat[i] = latent[i];
            s_dis[i] = g_disen[i];
        }
        __syncthreads();

        int u    = (b - ENTF_BLOCKS) * 8 + (threadIdx.x >> 5);
        int lane = threadIdx.x & 31;
        if (u >= N_USERS) return;

        float2 ue = *(const float2*)&user_emb[(size_t)u * CHANNEL + lane * 2];

        float s[N_FACTORS];
        #pragma unroll
        for (int f = 0; f < N_FACTORS; f++) {
            float p = ue.x * s_lat[f * CHANNEL + lane * 2]
                    + ue.y * s_lat[f * CHANNEL + lane * 2 + 1];
            #pragma unroll
            for (int o = 16; o > 0; o >>= 1) p += __shfl_xor_sync(0xFFFFFFFFu, p, o);
            s[f] = p;
        }
        float m = fmaxf(fmaxf(s[0], s[1]), fmaxf(s[2], s[3]));
        float sum = 0.0f;
        #pragma unroll
        for (int f = 0; f < N_FACTORS; f++) { s[f] = __expf(s[f] - m); sum += s[f]; }
        float inv = 1.0f / sum;

        float cx = 0.0f, cy = 0.0f;
        #pragma unroll
        for (int f = 0; f < N_FACTORS; f++) {
            float sc = s[f] * inv;
            cx += sc * s_dis[f * CHANNEL + lane * 2];
            cy += sc * s_dis[f * CHANNEL + lane * 2 + 1];
        }

        float2* p = (float2*)&out_user[(size_t)u * CHANNEL + lane * 2];
        float2 a = *p;
        a.x = a.x * (1.0f + cx);
        a.y = a.y * (1.0f + cy);
        *p = a;
    }
}

// ---------------------------------------------------------------------------
extern "C" void kernel_launch(void* const* d_in, const int* in_sizes, int n_in,
                              void* d_out, int out_size)
{
    const float* entity_emb = (const float*)d_in[0];
    const float* user_emb   = (const float*)d_in[1];
    const float* latent_emb = (const float*)d_in[2];
    const int*   head       = (const int*)d_in[3];
    const int*   tail       = (const int*)d_in[4];
    const int*   edge_type  = (const int*)d_in[5];
    const int*   mat_row    = (const int*)d_in[6];
    const int*   mat_col    = (const int*)d_in[7];
    const float* mat_val    = (const float*)d_in[8];
    const float* rel_w      = (const float*)d_in[9];
    const float* weight     = (const float*)d_in[10];
    const float* disen_att  = (const float*)d_in[11];

    float* out      = (float*)d_out;
    float* out_ent  = out;                                 // (N_ENTITIES, 64)
    float* out_user = out + (size_t)N_ENTITIES * CHANNEL;  // (N_USERS, 64)

    // Fork a side stream inside graph capture: spmm path is independent of
    // prep (att table), so it overlaps with prep on stream 0.
    cudaStream_t side;
    cudaStreamCreateWithFlags(&side, cudaStreamNonBlocking);
    cudaEvent_t ev_fork, ev_join;
    cudaEventCreateWithFlags(&ev_fork, cudaEventDisableTiming);
    cudaEventCreateWithFlags(&ev_join, cudaEventDisableTiming);

    cudaEventRecord(ev_fork, 0);
    cudaStreamWaitEvent(side, ev_fork, 0);

    // stream 0: prep -> edge scatter
    prep_kernel<<<PREP_BLOCKS, 256>>>(entity_emb, rel_w, disen_att, weight,
                                      (float4*)out_ent);
    edge_kernel<<<EDGE_BLOCKS, 256>>>(entity_emb, head, tail, edge_type,
                                      rel_w, out_ent);

    // side stream: zero user -> spmm scatter (overlaps with prep)
    zero_user_kernel<<<(N_USERS * CHANNEL / 4 + 255) / 256, 256, 0, side>>>(
        (float4*)out_user);
    spmm_kernel<<<SPMM_BLOCKS, 256, 0, side>>>(entity_emb, mat_row, mat_col,
                                               mat_val, out_user);

    cudaEventRecord(ev_join, side);
    cudaStreamWaitEvent(0, ev_join, 0);

    final_kernel<<<FINAL_BLOCKS, 256>>>(user_emb, latent_emb,
                                        (float4*)out_ent, out_user);
}

// round 11
// speedup vs baseline: 1.0838x; 1.0838x over previous
#include <cuda_runtime.h>
#include <cstdint>

#define N_ENTITIES 100000
#define N_USERS    50000
#define N_FACTORS  4
#define N_RELATIONS 32
#define N_REL_USED 31
#define N_META     8
#define CHANNEL    64
#define N_EDGES    1600000
#define NNZ_CNT    1000000

#define HW_PER_BLOCK 16                     // 256 threads / 16 lanes

// phase1 split: one wave at 4 blocks/SM (592 resident on 148 SMs)
#define SPMM_B  296
#define ATT_B   296
#define PHASE1_BLOCKS (SPMM_B + ATT_B + 1)  // +1 disen block (wave 2, tiny)

#define TILE_E 64
#define ATT_TILES ((N_ENTITIES + TILE_E - 1) / TILE_E)   // 1563

#define EDGE_BLOCKS 888

// final kernel split
#define ENTF_BLOCKS 6250
#define USERF_BLOCKS 6250
#define FINAL_BLOCKS (ENTF_BLOCKS + USERF_BLOCKS)

// ------------------------- device-global scratch ---------------------------
__device__ float g_cnt[N_ENTITIES];
__device__ float g_disen[N_FACTORS * CHANNEL];
__device__ float g_att[N_ENTITIES * N_REL_USED];   // sigmoid(ent[h] . rel[r])

__device__ __forceinline__ void red_add_v4(float* p, float x, float y, float z, float w) {
    asm volatile("red.global.add.v4.f32 [%0], {%1,%2,%3,%4};"
                 :: "l"(p), "f"(x), "f"(y), "f"(z), "f"(w) : "memory");
}

// ---------------------------------------------------------------------------
// 0) zero everything
// ---------------------------------------------------------------------------
__global__ void zero_kernel(float4* __restrict__ out) {
    int i = blockIdx.x * blockDim.x + threadIdx.x;
    const int total4 = (N_ENTITIES + N_USERS) * CHANNEL / 4;
    if (i < total4) out[i] = make_float4(0.f, 0.f, 0.f, 0.f);
    if (i < N_ENTITIES) g_cnt[i] = 0.0f;
}

// ---------------------------------------------------------------------------
// 1) PHASE1 (block-split, one wave): spmm scatter + cnt histogram | att | disen
//    spmm (atomic/LSU-bound) co-runs with att (FMA/LDS-bound).
//    att: channel-split two-pass, rrel[8] registers, <=64 regs/thread.
// ---------------------------------------------------------------------------
__global__ void __launch_bounds__(256, 4)
phase1_kernel(const float* __restrict__ ent,
              const int*   __restrict__ head,
              const int*   __restrict__ mrow,
              const int*   __restrict__ mcol,
              const float* __restrict__ mval,
              const float* __restrict__ relw,
              const float* __restrict__ datt,
              const float* __restrict__ weight,
              float* __restrict__ out_user) {
    int b = blockIdx.x;

    if (b < SPMM_B) {
        // ---- spmm scatter (half-warp per nnz) ----
        int li     = threadIdx.x & 15;
        int hw     = b * HW_PER_BLOCK + (threadIdx.x >> 4);
        int stride = SPMM_B * HW_PER_BLOCK;

        for (int i = hw; i < NNZ_CNT; i += stride) {
            int   r = __ldg(&mrow[i]);
            int   c = __ldg(&mcol[i]);
            float v = __ldg(&mval[i]);
            float4 e4 = __ldg((const float4*)&ent[(size_t)c * CHANNEL + li * 4]);
            red_add_v4(&out_user[(size_t)r * CHANNEL + li * 4],
                       v * e4.x, v * e4.y, v * e4.z, v * e4.w);
        }

        // ---- head-count histogram (thread per edge) ----
        int t0      = b * 256 + threadIdx.x;
        int tstride = SPMM_B * 256;
        for (int e = t0; e < N_EDGES; e += tstride) {
            int h = __ldg(&head[e]);
            asm volatile("red.global.add.f32 [%0], %1;"
                         :: "l"(&g_cnt[h]), "f"(1.0f) : "memory");
        }

    } else if (b < SPMM_B + ATT_B) {
        // ---- attention table: tile staging, channel-split two-pass ----
        __shared__ float s_ent[TILE_E * CHANNEL];     // 16 KB tile
        int lane = threadIdx.x & 31;
        int wid  = threadIdx.x >> 5;
        bool has_rel = (lane < N_REL_USED);
        const float4* rw = (const float4*)&relw[(has_rel ? lane : 0) * CHANNEL];

        int tile0 = b - SPMM_B;
        for (int tile = tile0; tile < ATT_TILES; tile += ATT_B) {
            int base = tile * TILE_E;
            int cnt  = min(TILE_E, N_ENTITIES - base);

            __syncthreads();                          // protect prior tile reads
            const float4* src = (const float4*)&ent[(size_t)base * CHANNEL];
            for (int i = threadIdx.x; i < cnt * (CHANNEL / 4); i += 256)
                ((float4*)s_ent)[i] = __ldg(&src[i]); // coalesced stream
            __syncthreads();

            float part[8];
            float4 rrel[8];

            // pass A: channels 0..31
            #pragma unroll
            for (int i = 0; i < 8; i++)
                rrel[i] = has_rel ? __ldg(&rw[i]) : make_float4(0.f, 0.f, 0.f, 0.f);
            #pragma unroll
            for (int k8 = 0; k8 < 8; k8++) {
                int k = wid + k8 * 8;
                const float4* row = (const float4*)&s_ent[k * CHANNEL];
                float d0 = 0.f, d1 = 0.f;
                #pragma unroll
                for (int i = 0; i < 8; i++) {
                    float4 a = row[i];                // broadcast LDS.128
                    d0 += a.x * rrel[i].x + a.z * rrel[i].z;
                    d1 += a.y * rrel[i].y + a.w * rrel[i].w;
                }
                part[k8] = d0 + d1;
            }

            // pass B: channels 32..63
            #pragma unroll
            for (int i = 0; i < 8; i++)
                rrel[i] = has_rel ? __ldg(&rw[8 + i]) : make_float4(0.f, 0.f, 0.f, 0.f);
            #pragma unroll
            for (int k8 = 0; k8 < 8; k8++) {
                int k = wid + k8 * 8;
                const float4* row = (const float4*)&s_ent[k * CHANNEL + 32];
                float d0 = 0.f, d1 = 0.f;
                #pragma unroll
                for (int i = 0; i < 8; i++) {
                    float4 a = row[i];
                    d0 += a.x * rrel[i].x + a.z * rrel[i].z;
                    d1 += a.y * rrel[i].y + a.w * rrel[i].w;
                }
                float d = part[k8] + d0 + d1;
                if (has_rel && k < cnt)
                    g_att[(size_t)(base + k) * N_REL_USED + lane] =
                        1.0f / (1.0f + __expf(-d));
            }
        }

    } else {
        // ---- disen_weight = softmax(disen_weight_att, -1) @ weight ----
        int c = threadIdx.x;
        if (c >= CHANNEL) return;
        #pragma unroll
        for (int f = 0; f < N_FACTORS; f++) {
            float a[N_META];
            float m = -1e30f;
            #pragma unroll
            for (int j = 0; j < N_META; j++) { a[j] = datt[f * N_META + j]; m = fmaxf(m, a[j]); }
            float s = 0.0f;
            #pragma unroll
            for (int j = 0; j < N_META; j++) { a[j] = __expf(a[j] - m); s += a[j]; }
            float inv = 1.0f / s;
            float acc = 0.0f;
            #pragma unroll
            for (int j = 0; j < N_META; j++) acc += a[j] * inv * weight[j * CHANNEL + c];
            g_disen[f * CHANNEL + c] = acc;
        }
    }
}

// ---------------------------------------------------------------------------
// 2) edge scatter: half-warp per edge, v4 reds only (cnt moved to phase1)
// ---------------------------------------------------------------------------
__global__ void __launch_bounds__(256)
edge_kernel(const float* __restrict__ ent,
            const int*   __restrict__ head,
            const int*   __restrict__ tail,
            const int*   __restrict__ etype,
            const float* __restrict__ relw,
            float* __restrict__ out_ent) {
    __shared__ float s_rel[N_REL_USED * CHANNEL];
    for (int i = threadIdx.x; i < N_REL_USED * CHANNEL; i += blockDim.x)
        s_rel[i] = relw[i];
    __syncthreads();

    int li     = threadIdx.x & 15;
    int hw     = blockIdx.x * HW_PER_BLOCK + (threadIdx.x >> 4);
    int stride = EDGE_BLOCKS * HW_PER_BLOCK;

    for (int e = hw; e < N_EDGES; e += stride) {
        int h  = __ldg(&head[e]);
        int t  = __ldg(&tail[e]);
        int ri = __ldg(&etype[e]) - 1;

        float  att = __ldg(&g_att[h * N_REL_USED + ri]);
        float4 rel = *(const float4*)&s_rel[ri * CHANNEL + li * 4];
        float4 et  = __ldg((const float4*)&ent[(size_t)t * CHANNEL + li * 4]);

        red_add_v4(&out_ent[(size_t)h * CHANNEL + li * 4],
                   att * et.x * rel.x, att * et.y * rel.y,
                   att * et.z * rel.z, att * et.w * rel.w);
    }
}

// ---------------------------------------------------------------------------
// 3) FINAL: entity mean-divide | user softmax-blend  (block-split)
// ---------------------------------------------------------------------------
__global__ void __launch_bounds__(256)
final_kernel(const float* __restrict__ user_emb,
             const float* __restrict__ latent,
             float4* __restrict__ out_ent4,
             float* __restrict__ out_user) {
    int b = blockIdx.x;

    if (b < ENTF_BLOCKS) {
        int i = b * 256 + threadIdx.x;
        if (i >= N_ENTITIES * (CHANNEL / 4)) return;
        float inv = 1.0f / fmaxf(g_cnt[i >> 4], 1.0f);
        float4 v = out_ent4[i];
        v.x *= inv; v.y *= inv; v.z *= inv; v.w *= inv;
        out_ent4[i] = v;

    } else {
        __shared__ float s_lat[N_FACTORS * CHANNEL];
        __shared__ float s_dis[N_FACTORS * CHANNEL];
        for (int i = threadIdx.x; i < N_FACTORS * CHANNEL; i += blockDim.x) {
            s_lat[i] = latent[i];
            s_dis[i] = g_disen[i];
        }
        __syncthreads();

        int u    = (b - ENTF_BLOCKS) * 8 + (threadIdx.x >> 5);
        int lane = threadIdx.x & 31;
        if (u >= N_USERS) return;

        float2 ue = *(const float2*)&user_emb[(size_t)u * CHANNEL + lane * 2];

        float s[N_FACTORS];
        #pragma unroll
        for (int f = 0; f < N_FACTORS; f++) {
            float p = ue.x * s_lat[f * CHANNEL + lane * 2]
                    + ue.y * s_lat[f * CHANNEL + lane * 2 + 1];
            #pragma unroll
            for (int o = 16; o > 0; o >>= 1) p += __shfl_xor_sync(0xFFFFFFFFu, p, o);
            s[f] = p;
        }
        float m = fmaxf(fmaxf(s[0], s[1]), fmaxf(s[2], s[3]));
        float sum = 0.0f;
        #pragma unroll
        for (int f = 0; f < N_FACTORS; f++) { s[f] = __expf(s[f] - m); sum += s[f]; }
        float inv = 1.0f / sum;

        float cx = 0.0f, cy = 0.0f;
        #pragma unroll
        for (int f = 0; f < N_FACTORS; f++) {
            float sc = s[f] * inv;
            cx += sc * s_dis[f * CHANNEL + lane * 2];
            cy += sc * s_dis[f * CHANNEL + lane * 2 + 1];
        }

        float2* p = (float2*)&out_user[(size_t)u * CHANNEL + lane * 2];
        float2 a = *p;
        a.x = a.x * (1.0f + cx);
        a.y = a.y * (1.0f + cy);
        *p = a;
    }
}

// ---------------------------------------------------------------------------
extern "C" void kernel_launch(void* const* d_in, const int* in_sizes, int n_in,
                              void* d_out, int out_size)
{
    const float* entity_emb = (const float*)d_in[0];
    const float* user_emb   = (const float*)d_in[1];
    const float* latent_emb = (const float*)d_in[2];
    const int*   head       = (const int*)d_in[3];
    const int*   tail       = (const int*)d_in[4];
    const int*   edge_type  = (const int*)d_in[5];
    const int*   mat_row    = (const int*)d_in[6];
    const int*   mat_col    = (const int*)d_in[7];
    const float* mat_val    = (const float*)d_in[8];
    const float* rel_w      = (const float*)d_in[9];
    const float* weight     = (const float*)d_in[10];
    const float* disen_att  = (const float*)d_in[11];

    float* out      = (float*)d_out;
    float* out_ent  = out;                                 // (N_ENTITIES, 64)
    float* out_user = out + (size_t)N_ENTITIES * CHANNEL;  // (N_USERS, 64)

    const int total4 = (N_ENTITIES + N_USERS) * CHANNEL / 4;
    zero_kernel<<<(total4 + 255) / 256, 256>>>((float4*)out);

    phase1_kernel<<<PHASE1_BLOCKS, 256>>>(entity_emb, head, mat_row, mat_col,
                                          mat_val, rel_w, disen_att, weight,
                                          out_user);

    edge_kernel<<<EDGE_BLOCKS, 256>>>(entity_emb, head, tail, edge_type,
                                      rel_w, out_ent);

    final_kernel<<<FINAL_BLOCKS, 256>>>(user_emb, latent_emb,
                                        (float4*)out_ent, out_user);
}